// round 2
// baseline (speedup 1.0000x reference)
#include <cuda_runtime.h>

#define IN_DIM  512
#define OUT_DIM 462
#define OUT_PAD 512
#define BROWS   65536

#define BM 128
#define BN 128
#define BK 16

// Scratch (allocation-free rule: __device__ globals)
__device__ float g_sx[BROWS];                 // per-row rsqrt scale for x
__device__ float g_Wp[IN_DIM * OUT_PAD];      // row-normalized W, padded to 512 cols

// ---------------------------------------------------------------------------
// Kernel 1: per-row sumsq of x -> sx[b] = rsqrt(max(sumsq, 1e-12))
// One warp per row (512 floats = 4 float4 per lane).
// ---------------------------------------------------------------------------
__global__ __launch_bounds__(256) void xnorm_kernel(const float* __restrict__ x) {
    int gwarp = (blockIdx.x * blockDim.x + threadIdx.x) >> 5;
    int lane  = threadIdx.x & 31;
    if (gwarp >= BROWS) return;
    const float4* xr = reinterpret_cast<const float4*>(x + (size_t)gwarp * IN_DIM);
    float s = 0.f;
#pragma unroll
    for (int i = 0; i < 4; i++) {
        float4 v = xr[lane + 32 * i];
        s += v.x * v.x + v.y * v.y + v.z * v.z + v.w * v.w;
    }
#pragma unroll
    for (int o = 16; o > 0; o >>= 1) s += __shfl_xor_sync(0xffffffffu, s, o);
    if (lane == 0) g_sx[gwarp] = rsqrtf(fmaxf(s, 1e-12f));
}

// ---------------------------------------------------------------------------
// Kernel 2: normalize each W row over OUT_DIM, write into padded g_Wp
// (pad cols [462,512) with zeros so GEMM B-loads are unpredicated float4).
// One block (128 threads) per W row.
// ---------------------------------------------------------------------------
__global__ __launch_bounds__(128) void wnorm_kernel(const float* __restrict__ W) {
    __shared__ float red[128];
    int i = blockIdx.x;
    int t = threadIdx.x;
    const float* wr = W + (size_t)i * OUT_DIM;
    float s = 0.f;
    for (int c = t; c < OUT_DIM; c += 128) { float v = wr[c]; s += v * v; }
    red[t] = s;
    __syncthreads();
#pragma unroll
    for (int o = 64; o > 0; o >>= 1) {
        if (t < o) red[t] += red[t + o];
        __syncthreads();
    }
    float sc = rsqrtf(fmaxf(red[0], 1e-12f));
    for (int c = t; c < OUT_PAD; c += 128)
        g_Wp[i * OUT_PAD + c] = (c < OUT_DIM) ? wr[c] * sc : 0.f;
}

// ---------------------------------------------------------------------------
// Kernel 3: SGEMM  out[b,o] = sx[b] * sum_k x[b,k] * Wp[k,o]
// 128x128 block tile, 8x8 thread tile, BK=16, register-prefetch pipeline.
// ---------------------------------------------------------------------------
__global__ __launch_bounds__(256) void gemm_kernel(const float* __restrict__ x,
                                                   float* __restrict__ out) {
    __shared__ float As[BK][BM];   // A transposed: As[k][m]
    __shared__ float Bs[BK][BN];

    const int tid = threadIdx.x;
    const int tx  = tid & 15;      // N-dim thread coord (0..15), 8 cols each
    const int ty  = tid >> 4;      // M-dim thread coord (0..15), 8 rows each
    const int m0  = blockIdx.y * BM;
    const int n0  = blockIdx.x * BN;

    const float* Ag = x + (size_t)m0 * IN_DIM;
    const float* Bg = g_Wp + n0;

    // A tile: 128 rows x 16 k = 512 float4; each thread loads 2 (rows arow, arow+64)
    const int arow = tid >> 2;           // 0..63
    const int akk  = (tid & 3) * 4;      // 0,4,8,12
    // B tile: 16 k-rows x 128 cols = 512 float4; each thread loads 2 (brow, brow+8)
    const int brow = tid >> 5;           // 0..7
    const int bcol = (tid & 31) * 4;     // 0..124

    float acc[8][8];
#pragma unroll
    for (int i = 0; i < 8; i++)
#pragma unroll
        for (int j = 0; j < 8; j++) acc[i][j] = 0.f;

    // ---- prologue: load tile 0 ----
    float4 ra0 = *reinterpret_cast<const float4*>(&Ag[(size_t)arow * IN_DIM + akk]);
    float4 ra1 = *reinterpret_cast<const float4*>(&Ag[(size_t)(arow + 64) * IN_DIM + akk]);
    float4 rb0 = *reinterpret_cast<const float4*>(&Bg[(size_t)brow * OUT_PAD + bcol]);
    float4 rb1 = *reinterpret_cast<const float4*>(&Bg[(size_t)(brow + 8) * OUT_PAD + bcol]);

    As[akk + 0][arow] = ra0.x; As[akk + 1][arow] = ra0.y;
    As[akk + 2][arow] = ra0.z; As[akk + 3][arow] = ra0.w;
    As[akk + 0][arow + 64] = ra1.x; As[akk + 1][arow + 64] = ra1.y;
    As[akk + 2][arow + 64] = ra1.z; As[akk + 3][arow + 64] = ra1.w;
    *reinterpret_cast<float4*>(&Bs[brow][bcol])     = rb0;
    *reinterpret_cast<float4*>(&Bs[brow + 8][bcol]) = rb1;
    __syncthreads();

    for (int k0 = BK; k0 < IN_DIM; k0 += BK) {
        // prefetch next tile into registers (overlaps with FMAs below)
        ra0 = *reinterpret_cast<const float4*>(&Ag[(size_t)arow * IN_DIM + k0 + akk]);
        ra1 = *reinterpret_cast<const float4*>(&Ag[(size_t)(arow + 64) * IN_DIM + k0 + akk]);
        rb0 = *reinterpret_cast<const float4*>(&Bg[(size_t)(k0 + brow) * OUT_PAD + bcol]);
        rb1 = *reinterpret_cast<const float4*>(&Bg[(size_t)(k0 + brow + 8) * OUT_PAD + bcol]);

        // compute current tile
#pragma unroll
        for (int k = 0; k < BK; k++) {
            float4 a0 = *reinterpret_cast<const float4*>(&As[k][ty * 8]);
            float4 a1 = *reinterpret_cast<const float4*>(&As[k][ty * 8 + 4]);
            float4 b0 = *reinterpret_cast<const float4*>(&Bs[k][tx * 8]);
            float4 b1 = *reinterpret_cast<const float4*>(&Bs[k][tx * 8 + 4]);
            float a[8] = {a0.x, a0.y, a0.z, a0.w, a1.x, a1.y, a1.z, a1.w};
            float b[8] = {b0.x, b0.y, b0.z, b0.w, b1.x, b1.y, b1.z, b1.w};
#pragma unroll
            for (int i = 0; i < 8; i++)
#pragma unroll
                for (int j = 0; j < 8; j++) acc[i][j] = fmaf(a[i], b[j], acc[i][j]);
        }
        __syncthreads();

        // commit prefetched tile
        As[akk + 0][arow] = ra0.x; As[akk + 1][arow] = ra0.y;
        As[akk + 2][arow] = ra0.z; As[akk + 3][arow] = ra0.w;
        As[akk + 0][arow + 64] = ra1.x; As[akk + 1][arow + 64] = ra1.y;
        As[akk + 2][arow + 64] = ra1.z; As[akk + 3][arow + 64] = ra1.w;
        *reinterpret_cast<float4*>(&Bs[brow][bcol])     = rb0;
        *reinterpret_cast<float4*>(&Bs[brow + 8][bcol]) = rb1;
        __syncthreads();
    }

    // last tile compute
#pragma unroll
    for (int k = 0; k < BK; k++) {
        float4 a0 = *reinterpret_cast<const float4*>(&As[k][ty * 8]);
        float4 a1 = *reinterpret_cast<const float4*>(&As[k][ty * 8 + 4]);
        float4 b0 = *reinterpret_cast<const float4*>(&Bs[k][tx * 8]);
        float4 b1 = *reinterpret_cast<const float4*>(&Bs[k][tx * 8 + 4]);
        float a[8] = {a0.x, a0.y, a0.z, a0.w, a1.x, a1.y, a1.z, a1.w};
        float b[8] = {b0.x, b0.y, b0.z, b0.w, b1.x, b1.y, b1.z, b1.w};
#pragma unroll
        for (int i = 0; i < 8; i++)
#pragma unroll
            for (int j = 0; j < 8; j++) acc[i][j] = fmaf(a[i], b[j], acc[i][j]);
    }

    // epilogue: scale by sx[row], predicated store (N=462)
#pragma unroll
    for (int i = 0; i < 8; i++) {
        int row = m0 + ty * 8 + i;
        float sc = g_sx[row];
#pragma unroll
        for (int j = 0; j < 8; j++) {
            int n = n0 + tx * 8 + j;
            if (n < OUT_DIM) out[(size_t)row * OUT_DIM + n] = acc[i][j] * sc;
        }
    }
}

// ---------------------------------------------------------------------------
extern "C" void kernel_launch(void* const* d_in, const int* in_sizes, int n_in,
                              void* d_out, int out_size) {
    // Expected order: x [65536*512], W [512*462]. Defensive size-based swap.
    const float* x = (const float*)d_in[0];
    const float* W = (const float*)d_in[1];
    if (in_sizes[0] == IN_DIM * OUT_DIM) { x = (const float*)d_in[1]; W = (const float*)d_in[0]; }
    float* out = (float*)d_out;

    xnorm_kernel<<<BROWS / 8, 256>>>(x);          // 8 warps/block
    wnorm_kernel<<<IN_DIM, 128>>>(W);
    dim3 grid(OUT_PAD / BN, BROWS / BM);          // (4, 512)
    gemm_kernel<<<grid, 256>>>(x, out);
}

// round 7
// speedup vs baseline: 2.5189x; 2.5189x over previous
#include <cuda_runtime.h>
#include <cuda_bf16.h>
#include <cstdint>

#define IN_DIM  512
#define OUT_DIM 462
#define BROWS   65536

// ---------------------------------------------------------------------------
// helpers
// ---------------------------------------------------------------------------
__device__ __forceinline__ uint32_t smem_u32(const void* p) {
    uint32_t a;
    asm("{ .reg .u64 t; cvta.to.shared.u64 t, %1; cvt.u32.u64 %0, t; }" : "=r"(a) : "l"(p));
    return a;
}

#define SW128(o) ((o) ^ (((o) >> 3) & 0x70))

#define STS128(a, r0, r1, r2, r3) \
    asm volatile("st.shared.v4.b32 [%0], {%1,%2,%3,%4};" :: "r"(a), "r"(r0), "r"(r1), "r"(r2), "r"(r3) : "memory")

#define CPA16(dst, src) \
    asm volatile("cp.async.cg.shared.global [%0], [%1], 16;" :: "r"(dst), "l"(src) : "memory")
#define CPA_COMMIT() asm volatile("cp.async.commit_group;" ::: "memory")
#define CPA_WAIT0()  asm volatile("cp.async.wait_group 0;" ::: "memory")

__device__ __forceinline__ void ldm_x4(uint32_t* r, uint32_t addr) {
    asm volatile("ldmatrix.sync.aligned.m8n8.x4.shared.b16 {%0,%1,%2,%3}, [%4];"
        : "=r"(r[0]), "=r"(r[1]), "=r"(r[2]), "=r"(r[3]) : "r"(addr));
}
__device__ __forceinline__ void mma_bf16(float* c, const uint32_t* a, const uint32_t* b) {
    asm volatile("mma.sync.aligned.m16n8k16.row.col.f32.bf16.bf16.f32 "
        "{%0,%1,%2,%3}, {%4,%5,%6,%7}, {%8,%9}, {%0,%1,%2,%3};"
        : "+f"(c[0]), "+f"(c[1]), "+f"(c[2]), "+f"(c[3])
        : "r"(a[0]), "r"(a[1]), "r"(a[2]), "r"(a[3]), "r"(b[0]), "r"(b[1]));
}

// ---------------------------------------------------------------------------
// Device scratch: normalized transposed W as bf16 hi/lo splits, B[n][k]
// n in [0,512) (rows >= 462 are zero), k in [0,512)
// ---------------------------------------------------------------------------
__device__ float          g_sw[IN_DIM];
__device__ __nv_bfloat16  g_whiT[IN_DIM * IN_DIM];
__device__ __nv_bfloat16  g_wloT[IN_DIM * IN_DIM];

__global__ __launch_bounds__(128) void wscale_kernel(const float* __restrict__ W) {
    __shared__ float red[128];
    int i = blockIdx.x, t = threadIdx.x;
    const float* wr = W + (size_t)i * OUT_DIM;
    float s = 0.f;
    for (int c = t; c < OUT_DIM; c += 128) { float v = wr[c]; s = fmaf(v, v, s); }
    red[t] = s;
    __syncthreads();
#pragma unroll
    for (int o = 64; o > 0; o >>= 1) { if (t < o) red[t] += red[t + o]; __syncthreads(); }
    if (t == 0) g_sw[i] = rsqrtf(fmaxf(red[0], 1e-12f));
}

__global__ __launch_bounds__(128) void wtrans_kernel(const float* __restrict__ W) {
    int n = blockIdx.x;
    for (int k = threadIdx.x; k < IN_DIM; k += 128) {
        float v = (n < OUT_DIM) ? W[(size_t)k * OUT_DIM + n] * g_sw[k] : 0.f;
        __nv_bfloat16 h = __float2bfloat16_rn(v);
        __nv_bfloat16 l = __float2bfloat16_rn(v - __bfloat162float(h));
        g_whiT[(size_t)n * IN_DIM + k] = h;
        g_wloT[(size_t)n * IN_DIM + k] = l;
    }
}

// ---------------------------------------------------------------------------
// Main GEMM: CTA = 128 rows x 128 cols, K = 512 in 8 chunks of 64.
// Per chunk: cp.async B hi/lo, LDG+convert A hi/lo (+fused sumsq), then
// mma.sync bf16 3-term split accumulating in fp32 registers.
// ---------------------------------------------------------------------------
#define SM_AHI  0
#define SM_ALO  16384
#define SM_BHI  32768
#define SM_BLO  49152
#define SM_RED  65536          // 256 floats
#define SM_SXS  66560          // 128 floats
#define SM_TOTAL 67072

__global__ __launch_bounds__(256, 2) void gemm_kernel(const float* __restrict__ x,
                                                      float* __restrict__ out) {
    extern __shared__ __align__(1024) unsigned char smem[];
    uint32_t sb = smem_u32(smem);
    const int tid  = threadIdx.x;
    const int lane = tid & 31;
    const int warp = tid >> 5;
    const int wm   = warp >> 1;          // 0..3
    const int wn   = warp & 1;           // 0..1
    const int n0   = blockIdx.x * 128;
    const int m0   = blockIdx.y * 128;

    float acc[2][8][4];
#pragma unroll
    for (int a = 0; a < 2; a++)
#pragma unroll
        for (int b = 0; b < 8; b++)
#pragma unroll
            for (int c = 0; c < 4; c++) acc[a][b][c] = 0.f;

    // A loader mapping: thread t -> row t>>1, half t&1 (32 floats per chunk)
    const int ar = tid >> 1;
    const int ah = tid & 1;
    const float4* xsrc = reinterpret_cast<const float4*>(x + (size_t)(m0 + ar) * IN_DIM) + ah * 8;
    const uint32_t a_row_base = (uint32_t)(ar * 128 + ah * 64);

    // B loader mapping: thread t -> n row t&127, half t>>7 (4 x 16B per buffer)
    const int bn  = tid & 127;
    const int bh2 = tid >> 7;
    const char* bsrc_hi = reinterpret_cast<const char*>(g_whiT) + (size_t)(n0 + bn) * 1024 + bh2 * 64;
    const char* bsrc_lo = reinterpret_cast<const char*>(g_wloT) + (size_t)(n0 + bn) * 1024 + bh2 * 64;
    const uint32_t b_row_base = (uint32_t)(bn * 128 + bh2 * 64);

    float sumsq = 0.f;

#pragma unroll 1
    for (int c = 0; c < 8; c++) {
        // --- B tiles via cp.async ---
#pragma unroll
        for (int j = 0; j < 4; j++)
            CPA16(sb + SM_BHI + SW128(b_row_base + j * 16), bsrc_hi + c * 128 + j * 16);
#pragma unroll
        for (int j = 0; j < 4; j++)
            CPA16(sb + SM_BLO + SW128(b_row_base + j * 16), bsrc_lo + c * 128 + j * 16);
        CPA_COMMIT();

        // --- A tile: LDG fp32, fused sumsq, split to bf16 hi/lo, STS ---
        float4 v[8];
#pragma unroll
        for (int i = 0; i < 8; i++) v[i] = xsrc[c * 16 + i];
#pragma unroll
        for (int i = 0; i < 8; i++) {
            sumsq = fmaf(v[i].x, v[i].x, sumsq); sumsq = fmaf(v[i].y, v[i].y, sumsq);
            sumsq = fmaf(v[i].z, v[i].z, sumsq); sumsq = fmaf(v[i].w, v[i].w, sumsq);
        }
#pragma unroll
        for (int j = 0; j < 4; j++) {
            float f[8] = {v[2*j].x, v[2*j].y, v[2*j].z, v[2*j].w,
                          v[2*j+1].x, v[2*j+1].y, v[2*j+1].z, v[2*j+1].w};
            uint32_t hu[4], lu[4];
#pragma unroll
            for (int e = 0; e < 4; e++) {
                __nv_bfloat16 h0 = __float2bfloat16_rn(f[2*e]);
                __nv_bfloat16 h1 = __float2bfloat16_rn(f[2*e+1]);
                __nv_bfloat16 l0 = __float2bfloat16_rn(f[2*e]   - __bfloat162float(h0));
                __nv_bfloat16 l1 = __float2bfloat16_rn(f[2*e+1] - __bfloat162float(h1));
                __nv_bfloat162 hp = __halves2bfloat162(h0, h1);
                __nv_bfloat162 lp = __halves2bfloat162(l0, l1);
                hu[e] = *reinterpret_cast<uint32_t*>(&hp);
                lu[e] = *reinterpret_cast<uint32_t*>(&lp);
            }
            uint32_t off = SW128(a_row_base + j * 16);
            STS128(sb + SM_AHI + off, hu[0], hu[1], hu[2], hu[3]);
            STS128(sb + SM_ALO + off, lu[0], lu[1], lu[2], lu[3]);
        }

        CPA_WAIT0();
        __syncthreads();

        // --- MMA: 4 k16 steps, 3-term split ---
#pragma unroll
        for (int kk = 0; kk < 4; kk++) {
            uint32_t ahi[2][4], alo[2][4];
#pragma unroll
            for (int tm = 0; tm < 2; tm++) {
                uint32_t offa = SW128((uint32_t)((wm * 32 + tm * 16 + (lane & 15)) * 128
                                                 + kk * 32 + ((lane >> 4) << 4)));
                ldm_x4(ahi[tm], sb + SM_AHI + offa);
                ldm_x4(alo[tm], sb + SM_ALO + offa);
            }
#pragma unroll
            for (int nb = 0; nb < 4; nb++) {
                // B stored [n][k] row-major == col-major operand for row.col mma.
                // Non-trans ldmatrix: r0,r1 = (n octet 0, k0-7/k8-15), r2,r3 = n octet 1.
                uint32_t offb = SW128((uint32_t)((wn * 64 + nb * 16 + (lane & 7) + ((lane >> 4) << 3)) * 128
                                                 + kk * 32 + (((lane >> 3) & 1) << 4)));
                uint32_t bh[4], bl[4];
                ldm_x4(bh, sb + SM_BHI + offb);
                ldm_x4(bl, sb + SM_BLO + offb);
#pragma unroll
                for (int tm = 0; tm < 2; tm++) {
                    mma_bf16(acc[tm][2*nb],   ahi[tm], bh);
                    mma_bf16(acc[tm][2*nb],   alo[tm], bh);
                    mma_bf16(acc[tm][2*nb],   ahi[tm], bl);
                    mma_bf16(acc[tm][2*nb+1], ahi[tm], bh + 2);
                    mma_bf16(acc[tm][2*nb+1], alo[tm], bh + 2);
                    mma_bf16(acc[tm][2*nb+1], ahi[tm], bl + 2);
                }
            }
        }
        __syncthreads();
    }

    // --- per-row rsqrt scale (two half-row partials per row) ---
    float* red = reinterpret_cast<float*>(smem + SM_RED);
    float* sxs = reinterpret_cast<float*>(smem + SM_SXS);
    red[tid] = sumsq;
    __syncthreads();
    if (tid < 128) sxs[tid] = rsqrtf(fmaxf(red[2 * tid] + red[2 * tid + 1], 1e-12f));
    __syncthreads();

    // --- epilogue: scale + predicated float2 stores ---
#pragma unroll
    for (int tm = 0; tm < 2; tm++) {
        int rl = wm * 32 + tm * 16 + (lane >> 2);
        float s0 = sxs[rl];
        float s1 = sxs[rl + 8];
        float* o0 = out + (size_t)(m0 + rl) * OUT_DIM;
        float* o1 = out + (size_t)(m0 + rl + 8) * OUT_DIM;
#pragma unroll
        for (int nt = 0; nt < 8; nt++) {
            int cg = n0 + wn * 64 + nt * 8 + (lane & 3) * 2;
            if (cg + 2 <= OUT_DIM) {
                float2 v0 = make_float2(acc[tm][nt][0] * s0, acc[tm][nt][1] * s0);
                float2 v1 = make_float2(acc[tm][nt][2] * s1, acc[tm][nt][3] * s1);
                *reinterpret_cast<float2*>(o0 + cg) = v0;
                *reinterpret_cast<float2*>(o1 + cg) = v1;
            }
        }
    }
}

// ---------------------------------------------------------------------------
extern "C" void kernel_launch(void* const* d_in, const int* in_sizes, int n_in,
                              void* d_out, int out_size) {
    const float* x = (const float*)d_in[0];
    const float* W = (const float*)d_in[1];
    if (in_sizes[0] == IN_DIM * OUT_DIM) { x = (const float*)d_in[1]; W = (const float*)d_in[0]; }
    float* out = (float*)d_out;

    cudaFuncSetAttribute(gemm_kernel, cudaFuncAttributeMaxDynamicSharedMemorySize, SM_TOTAL);

    wscale_kernel<<<IN_DIM, 128>>>(W);
    wtrans_kernel<<<IN_DIM, 128>>>(W);
    dim3 grid(4, BROWS / 128);
    gemm_kernel<<<grid, 256, SM_TOTAL>>>(x, out);
}